// round 14
// baseline (speedup 1.0000x reference)
#include <cuda_runtime.h>
#include <cuda_fp16.h>
#include <cstdint>

// ============================================================================
// R14: two counter-chained launches (shallow dependency chains only):
//  launch 1 (mega):  QKproj(1024) + Vproj(512) + QK(1024, spins on Q/K blocks)
//  launch 2 (mega2): softmax(1024 CTAs x 8 rows, no spin) +
//                    PV(512 tiles, spin on P row-block; Vt complete)
// R13 showed deep chains stall residency slots; R12 showed shallow chains win.
// Math identical to R10/R12 -> rel_err 5.856e-4.
// ============================================================================

using fp16 = __half;

// ---------------- scratch ----------------------------------------------------
__device__ __align__(256) fp16 g_x[8192 * 1024];
__device__ __align__(256) fp16 g_W[3 * 1024 * 1024];
__device__ __align__(256) fp16 g_Q[8192 * 1024];
__device__ __align__(256) fp16 g_K[8192 * 1024];
__device__ __align__(256) fp16 g_Vt[4 * 1024 * 2048];        // transposed
__device__ __align__(256) float g_S[4 * 2048 * 2048];
__device__ __align__(256) fp16 g_P[4 * 2048 * 2048];
// counters: [0,64) Q row-blocks, [64,128) K row-blocks, [192,256) P row-blocks
__device__ int g_cnt[256];

// ---------------- PTX helpers -------------------------------------------------
__device__ __forceinline__ uint32_t smem_u32(const void* p) {
    uint32_t a;
    asm("{ .reg .u64 t; cvta.to.shared.u64 t, %1; cvt.u32.u64 %0, t; }" : "=r"(a) : "l"(p));
    return a;
}
__device__ __forceinline__ void cp16(uint32_t dst, const void* src) {
    asm volatile("cp.async.cg.shared.global [%0], [%1], 16;" :: "r"(dst), "l"(src));
}
#define CP_COMMIT() asm volatile("cp.async.commit_group;" ::: "memory")

__device__ __forceinline__ void ldm4(uint32_t* r, uint32_t a) {
    asm volatile("ldmatrix.sync.aligned.m8n8.x4.shared.b16 {%0,%1,%2,%3}, [%4];"
                 : "=r"(r[0]), "=r"(r[1]), "=r"(r[2]), "=r"(r[3]) : "r"(a));
}
__device__ __forceinline__ void mma_f16(float* c, const uint32_t* a, uint32_t b0, uint32_t b1) {
    asm volatile(
        "mma.sync.aligned.m16n8k16.row.col.f32.f16.f16.f32 "
        "{%0,%1,%2,%3}, {%4,%5,%6,%7}, {%8,%9}, {%0,%1,%2,%3};"
        : "+f"(c[0]), "+f"(c[1]), "+f"(c[2]), "+f"(c[3])
        : "r"(a[0]), "r"(a[1]), "r"(a[2]), "r"(a[3]), "r"(b0), "r"(b1));
}
__device__ __forceinline__ int ld_acq(const int* p) {
    int v;
    asm volatile("ld.acquire.gpu.global.b32 %0, [%1];" : "=r"(v) : "l"(p) : "memory");
    return v;
}
__device__ __forceinline__ void spin_until(const int* c, int target) {
    if (threadIdx.x == 0) {
        while (ld_acq(c) < target) __nanosleep(64);
    }
}
__device__ __forceinline__ void arrive(int idx) {
    __threadfence();
    __syncthreads();
    if (threadIdx.x == 0) atomicAdd(&g_cnt[idx], 1);
}

// ---------------- SMEM layout -------------------------------------------------
// Per stage: A, B — each 128 rows x 64 fp16 (128B data), row stride 144B.
// ldmatrix phase (8 rows): banks 36r ≡ 4r mod 32, distinct. Conflict-free.
#define ROWB     144
#define ARR_B    (128 * ROWB)          // 18432
#define STG_B    (2 * ARR_B)           // 36864
#define SM_TOTAL (2 * STG_B)           // 73728

// ---------------- GEMM body: 128x128 tile, 256 thr, warps 2(m) x 4(n) --------
// MODE 0: QKV (z: 0->Q, 1->K, 2->V transposed) -> fp16
// MODE 1: QK  (z=batch), g_S = acc/32 fp32
// MODE 2: PV  (z=batch), out = acc fp32
template <int MODE>
__device__ __forceinline__ void gemm_body(
    const fp16* __restrict__ A, int lda,
    const fp16* __restrict__ B, int ldb,
    int K, float* __restrict__ outp,
    int bx, int by, int z)
{
    extern __shared__ char sm[];
    const uint32_t smb = smem_u32(sm);
    const int tid = threadIdx.x, lane = tid & 31, wid = tid >> 5;
    const int wm = wid & 1, wn = wid >> 1;          // warp tile: 64x32
    const int row0 = by * 128, col0 = bx * 128;

    float acc[4][4][4];
    #pragma unroll
    for (int i = 0; i < 4; ++i)
        #pragma unroll
        for (int j = 0; j < 4; ++j)
            #pragma unroll
            for (int k = 0; k < 4; ++k) acc[i][j][k] = 0.f;

    const fp16* pa = A + (size_t)row0 * lda;
    const fp16* pb = B + (size_t)col0 * ldb;

    auto load_stage = [&](int sbuf, int k0) {
        const uint32_t b = smb + sbuf * STG_B;
        #pragma unroll
        for (int v = 0; v < 4; ++v) {
            const int idx = tid + v * 256;       // 0..1023
            const int row = idx >> 3;            // 0..127
            const int kc  = idx & 7;             // 16B unit
            const uint32_t so = row * ROWB + kc * 16;
            cp16(b + so,         pa + (size_t)row * lda + k0 + kc * 8);
            cp16(b + ARR_B + so, pb + (size_t)row * ldb + k0 + kc * 8);
        }
        CP_COMMIT();
    };

    const int ns = K >> 6;   // 64 K per stage
    load_stage(0, 0);

    const uint32_t a_off = (wm * 64 + (lane & 15)) * ROWB + (lane >> 4) * 16;
    const uint32_t b_off = ARR_B
                         + (wn * 32 + (lane & 7) + ((lane >> 4) << 3)) * ROWB
                         + ((lane >> 3) & 1) * 16;

    for (int s = 0; s < ns; ++s) {
        if (s + 1 < ns) {
            load_stage((s + 1) & 1, (s + 1) * 64);
            asm volatile("cp.async.wait_group 1;" ::: "memory");
        } else {
            asm volatile("cp.async.wait_group 0;" ::: "memory");
        }
        __syncthreads();

        const uint32_t sb = smb + (s & 1) * STG_B;
        #pragma unroll
        for (int ks = 0; ks < 4; ++ks) {         // 4 k16 slices per stage
            const uint32_t ab = sb + a_off + ks * 32;
            const uint32_t bb = sb + b_off + ks * 32;
            uint32_t af[4][4], bf[2][4];
            #pragma unroll
            for (int mt = 0; mt < 4; ++mt)
                ldm4(af[mt], ab + mt * 16 * ROWB);
            #pragma unroll
            for (int bt = 0; bt < 2; ++bt)
                ldm4(bf[bt], bb + bt * 16 * ROWB);
            #pragma unroll
            for (int mt = 0; mt < 4; ++mt)
                #pragma unroll
                for (int nt = 0; nt < 4; ++nt) {
                    const int bt = nt >> 1, h = (nt & 1) * 2;
                    mma_f16(acc[mt][nt], af[mt], bf[bt][h], bf[bt][h + 1]);
                }
        }
        __syncthreads();
    }

    // ---- epilogue ----
    const int gr0 = row0 + wm * 64 + (lane >> 2);
    const int gc0 = col0 + wn * 32 + (lane & 3) * 2;

    #pragma unroll
    for (int mt = 0; mt < 4; ++mt)
        #pragma unroll
        for (int nt = 0; nt < 4; ++nt) {
            const int gr = gr0 + mt * 16;
            const int gc = gc0 + nt * 8;
            const float* c = acc[mt][nt];
            if (MODE == 0) {
                if (z == 2) {            // V: fp16, transposed Vt[(b*1024+n)][t]
                    const int b = gr >> 11, t = gr & 2047;
                    const size_t o = ((size_t)(b * 1024 + gc)) * 2048 + t;
                    g_Vt[o]            = __float2half(c[0]);
                    g_Vt[o + 2048]     = __float2half(c[1]);
                    g_Vt[o + 8]        = __float2half(c[2]);
                    g_Vt[o + 2048 + 8] = __float2half(c[3]);
                } else {                 // Q or K: fp16 row-major
                    fp16* d = (z == 0) ? g_Q : g_K;
                    const size_t o = (size_t)gr * 1024 + gc;
                    *(__half2*)(d + o)            = __floats2half2_rn(c[0], c[1]);
                    *(__half2*)(d + o + 8 * 1024) = __floats2half2_rn(c[2], c[3]);
                }
            } else if (MODE == 1) {
                float* p = g_S + ((size_t)z << 22) + (size_t)gr * 2048 + gc;
                *(float2*)p              = make_float2(c[0] * 0.03125f, c[1] * 0.03125f);
                *(float2*)(p + 8 * 2048) = make_float2(c[2] * 0.03125f, c[3] * 0.03125f);
            } else {
                float* p = outp + ((size_t)z << 21) + (size_t)gr * 1024 + gc;
                *(float2*)p              = make_float2(c[0], c[1]);
                *(float2*)(p + 8 * 1024) = make_float2(c[2], c[3]);
            }
        }
}

// ---------------- softmax: one row (256 thr, 8 elems/thr) ---------------------
__device__ __forceinline__ void softmax_row(int rowid, float* red)
{
    size_t ro = (size_t)rowid * 2048;
    const float* p = g_S + ro;
    const int t = threadIdx.x;

    float v[8];
    float m = -1e30f;
    #pragma unroll
    for (int i = 0; i < 8; ++i) {
        v[i] = p[t + i * 256];
        m = fmaxf(m, v[i]);
    }
    #pragma unroll
    for (int o = 16; o; o >>= 1) m = fmaxf(m, __shfl_xor_sync(0xffffffffu, m, o));
    if ((t & 31) == 0) red[t >> 5] = m;
    __syncthreads();
    m = red[0];
    #pragma unroll
    for (int i = 1; i < 8; ++i) m = fmaxf(m, red[i]);
    __syncthreads();

    float s = 0.f;
    #pragma unroll
    for (int i = 0; i < 8; ++i) {
        v[i] = __expf(v[i] - m);
        s += v[i];
    }
    #pragma unroll
    for (int o = 16; o; o >>= 1) s += __shfl_xor_sync(0xffffffffu, s, o);
    if ((t & 31) == 0) red[t >> 5] = s;
    __syncthreads();
    s = red[0];
    #pragma unroll
    for (int i = 1; i < 8; ++i) s += red[i];

    const float inv = 1.0f / s;
    #pragma unroll
    for (int i = 0; i < 8; ++i) {
        size_t o = ro + t + i * 256;
        g_P[o] = __float2half(v[i] * inv);
    }
    __syncthreads();   // red[] reused by next row
}

// ---------------- launch 1: QKV projections + QK gemm -------------------------
__global__ void __launch_bounds__(256)
mega_kernel()
{
    const int b = blockIdx.x;
    if (b < 1024) {                     // Q/K projections: z = b/512
        const int z = b >> 9, r = b & 511;
        const int by = r >> 3;
        gemm_body<0>(g_x, 1024, g_W + (size_t)z * 1024 * 1024, 1024,
                     1024, nullptr, r & 7, by, z);
        arrive(z * 64 + by);
    } else if (b < 1536) {              // V projection (no consumers in launch 1)
        const int r = b - 1024;
        gemm_body<0>(g_x, 1024, g_W + (size_t)2 * 1024 * 1024, 1024,
                     1024, nullptr, r & 7, r >> 3, 2);
    } else {                            // QK tiles, spin on Q/K row blocks
        const int j = b - 1536;
        const int z = j >> 8, by = (j >> 4) & 15, bx = j & 15;
        spin_until(&g_cnt[z * 16 + by], 8);          // Q row-block
        spin_until(&g_cnt[64 + z * 16 + bx], 8);     // K row-block
        __syncthreads();
        const size_t bo = (size_t)z << 21;
        gemm_body<1>(g_Q + bo, 1024, g_K + bo, 1024, 1024, nullptr, bx, by, z);
    }
}

// ---------------- launch 2: softmax + PV --------------------------------------
__global__ void __launch_bounds__(256)
mega2_kernel(float* __restrict__ out)
{
    const int b = blockIdx.x;
    if (b < 1024) {                     // softmax: 8 rows per CTA (no spin)
        const int rb = b >> 4;                       // P row-block 0..63
        __shared__ float red[8];
        const int row0 = rb * 128 + (b & 15) * 8;
        #pragma unroll 1
        for (int r = 0; r < 8; ++r) softmax_row(row0 + r, red);
        arrive(192 + rb);                            // 16 arrivals per row-block
    } else {                            // PV tiles, spin on P row-block
        const int j = b - 1024;                      // 0..511
        const int z = j >> 7, rem = j & 127;
        const int by = rem >> 3, bx = rem & 7;
        spin_until(&g_cnt[192 + z * 16 + by], 16);
        __syncthreads();
        const size_t ao = (size_t)z << 22;
        const size_t bo = (size_t)z << 21;
        gemm_body<2>(g_P + ao, 2048, g_Vt + bo, 2048, 2048, out, bx, by, z);
    }
}

// One launch converting x then Wq/Wk/Wv; block 0 also zeroes the dep counters.
#define N4_X (8192 * 1024 / 4)
#define N4_W (1024 * 1024 / 4)
__global__ void __launch_bounds__(256)
convert_all_kernel(const float* __restrict__ x, const float* __restrict__ Wq,
                   const float* __restrict__ Wk, const float* __restrict__ Wv)
{
    if (blockIdx.x == 0) {
        for (int i = threadIdx.x; i < 256; i += 256) g_cnt[i] = 0;
    }

    const int i = blockIdx.x * blockDim.x + threadIdx.x;
    const float* src;
    fp16* dst;
    int k;
    if (i < N4_X) {
        src = x; dst = g_x; k = i;
    } else {
        int j = i - N4_X;
        int w = j / N4_W;
        k = j - w * N4_W;
        src = (w == 0) ? Wq : (w == 1) ? Wk : Wv;
        dst = g_W + (size_t)w * 1024 * 1024;
    }
    float4 v = *(const float4*)(src + (size_t)k * 4);
    __half2* d = (__half2*)(dst + (size_t)k * 4);
    d[0] = __floats2half2_rn(v.x, v.y);
    d[1] = __floats2half2_rn(v.z, v.w);
}

// ---------------- launch ------------------------------------------------------
extern "C" void kernel_launch(void* const* d_in, const int* in_sizes, int n_in,
                              void* d_out, int out_size)
{
    const float* x  = (const float*)d_in[0];
    const float* Wq = (const float*)d_in[1];
    const float* Wk = (const float*)d_in[2];
    const float* Wv = (const float*)d_in[3];
    float* out = (float*)d_out;

    cudaFuncSetAttribute(mega_kernel,  cudaFuncAttributeMaxDynamicSharedMemorySize, SM_TOTAL);
    cudaFuncSetAttribute(mega2_kernel, cudaFuncAttributeMaxDynamicSharedMemorySize, SM_TOTAL);

    {
        int n4 = N4_X + 3 * N4_W;
        convert_all_kernel<<<(n4 + 255) / 256, 256>>>(x, Wq, Wk, Wv);
    }

    // launch 1: QKproj(1024) + Vproj(512) + QK(1024)
    mega_kernel<<<2560, 256, SM_TOTAL>>>();

    // launch 2: softmax(1024) + PV(512)
    mega2_kernel<<<1536, 256, SM_TOTAL>>>(out);
}

// round 15
// speedup vs baseline: 1.0140x; 1.0140x over previous
#include <cuda_runtime.h>
#include <cuda_fp16.h>
#include <cstdint>

// ============================================================================
// R15: R12 + softmax fused into the mega kernel as trailing dependent blocks:
//  launch 1 (mega): QKproj(1024) + Vproj(512) + QK(1024, spins on Q/K blocks,
//                   arrives on S row-block) + softmax(1024, spins on S blocks)
//  launch 2: PV (512 tiles, standard grid — R14 showed PV spinners regress).
// Softmax blocks have the highest indices: they reach SMs only during the
// final QK waves (producer-adjacent spinning, the regime that worked in R12).
// Math identical to R10/R12 -> rel_err 5.856e-4.
// ============================================================================

using fp16 = __half;

// ---------------- scratch ----------------------------------------------------
__device__ __align__(256) fp16 g_x[8192 * 1024];
__device__ __align__(256) fp16 g_W[3 * 1024 * 1024];
__device__ __align__(256) fp16 g_Q[8192 * 1024];
__device__ __align__(256) fp16 g_K[8192 * 1024];
__device__ __align__(256) fp16 g_Vt[4 * 1024 * 2048];        // transposed
__device__ __align__(256) float g_S[4 * 2048 * 2048];
__device__ __align__(256) fp16 g_P[4 * 2048 * 2048];
// counters: [0,64) Q row-blocks, [64,128) K row-blocks, [128,192) S row-blocks
__device__ int g_cnt[192];

// ---------------- PTX helpers -------------------------------------------------
__device__ __forceinline__ uint32_t smem_u32(const void* p) {
    uint32_t a;
    asm("{ .reg .u64 t; cvta.to.shared.u64 t, %1; cvt.u32.u64 %0, t; }" : "=r"(a) : "l"(p));
    return a;
}
__device__ __forceinline__ void cp16(uint32_t dst, const void* src) {
    asm volatile("cp.async.cg.shared.global [%0], [%1], 16;" :: "r"(dst), "l"(src));
}
#define CP_COMMIT() asm volatile("cp.async.commit_group;" ::: "memory")

__device__ __forceinline__ void ldm4(uint32_t* r, uint32_t a) {
    asm volatile("ldmatrix.sync.aligned.m8n8.x4.shared.b16 {%0,%1,%2,%3}, [%4];"
                 : "=r"(r[0]), "=r"(r[1]), "=r"(r[2]), "=r"(r[3]) : "r"(a));
}
__device__ __forceinline__ void mma_f16(float* c, const uint32_t* a, uint32_t b0, uint32_t b1) {
    asm volatile(
        "mma.sync.aligned.m16n8k16.row.col.f32.f16.f16.f32 "
        "{%0,%1,%2,%3}, {%4,%5,%6,%7}, {%8,%9}, {%0,%1,%2,%3};"
        : "+f"(c[0]), "+f"(c[1]), "+f"(c[2]), "+f"(c[3])
        : "r"(a[0]), "r"(a[1]), "r"(a[2]), "r"(a[3]), "r"(b0), "r"(b1));
}
__device__ __forceinline__ int ld_acq(const int* p) {
    int v;
    asm volatile("ld.acquire.gpu.global.b32 %0, [%1];" : "=r"(v) : "l"(p) : "memory");
    return v;
}
__device__ __forceinline__ void spin_until(const int* c, int target) {
    if (threadIdx.x == 0) {
        while (ld_acq(c) < target) __nanosleep(64);
    }
}
__device__ __forceinline__ void arrive(int idx) {
    __threadfence();
    __syncthreads();
    if (threadIdx.x == 0) atomicAdd(&g_cnt[idx], 1);
}

// ---------------- SMEM layout -------------------------------------------------
// Per stage: A, B — each 128 rows x 64 fp16 (128B data), row stride 144B.
// ldmatrix phase (8 rows): banks 36r ≡ 4r mod 32, distinct. Conflict-free.
#define ROWB     144
#define ARR_B    (128 * ROWB)          // 18432
#define STG_B    (2 * ARR_B)           // 36864
#define SM_TOTAL (2 * STG_B)           // 73728

// ---------------- GEMM body: 128x128 tile, 256 thr, warps 2(m) x 4(n) --------
// MODE 0: QKV (z: 0->Q, 1->K, 2->V transposed) -> fp16
// MODE 1: QK  (z=batch), g_S = acc/32 fp32
// MODE 2: PV  (z=batch), out = acc fp32
template <int MODE>
__device__ __forceinline__ void gemm_body(
    const fp16* __restrict__ A, int lda,
    const fp16* __restrict__ B, int ldb,
    int K, float* __restrict__ outp,
    int bx, int by, int z)
{
    extern __shared__ char sm[];
    const uint32_t smb = smem_u32(sm);
    const int tid = threadIdx.x, lane = tid & 31, wid = tid >> 5;
    const int wm = wid & 1, wn = wid >> 1;          // warp tile: 64x32
    const int row0 = by * 128, col0 = bx * 128;

    float acc[4][4][4];
    #pragma unroll
    for (int i = 0; i < 4; ++i)
        #pragma unroll
        for (int j = 0; j < 4; ++j)
            #pragma unroll
            for (int k = 0; k < 4; ++k) acc[i][j][k] = 0.f;

    const fp16* pa = A + (size_t)row0 * lda;
    const fp16* pb = B + (size_t)col0 * ldb;

    auto load_stage = [&](int sbuf, int k0) {
        const uint32_t b = smb + sbuf * STG_B;
        #pragma unroll
        for (int v = 0; v < 4; ++v) {
            const int idx = tid + v * 256;       // 0..1023
            const int row = idx >> 3;            // 0..127
            const int kc  = idx & 7;             // 16B unit
            const uint32_t so = row * ROWB + kc * 16;
            cp16(b + so,         pa + (size_t)row * lda + k0 + kc * 8);
            cp16(b + ARR_B + so, pb + (size_t)row * ldb + k0 + kc * 8);
        }
        CP_COMMIT();
    };

    const int ns = K >> 6;   // 64 K per stage
    load_stage(0, 0);

    const uint32_t a_off = (wm * 64 + (lane & 15)) * ROWB + (lane >> 4) * 16;
    const uint32_t b_off = ARR_B
                         + (wn * 32 + (lane & 7) + ((lane >> 4) << 3)) * ROWB
                         + ((lane >> 3) & 1) * 16;

    for (int s = 0; s < ns; ++s) {
        if (s + 1 < ns) {
            load_stage((s + 1) & 1, (s + 1) * 64);
            asm volatile("cp.async.wait_group 1;" ::: "memory");
        } else {
            asm volatile("cp.async.wait_group 0;" ::: "memory");
        }
        __syncthreads();

        const uint32_t sb = smb + (s & 1) * STG_B;
        #pragma unroll
        for (int ks = 0; ks < 4; ++ks) {         // 4 k16 slices per stage
            const uint32_t ab = sb + a_off + ks * 32;
            const uint32_t bb = sb + b_off + ks * 32;
            uint32_t af[4][4], bf[2][4];
            #pragma unroll
            for (int mt = 0; mt < 4; ++mt)
                ldm4(af[mt], ab + mt * 16 * ROWB);
            #pragma unroll
            for (int bt = 0; bt < 2; ++bt)
                ldm4(bf[bt], bb + bt * 16 * ROWB);
            #pragma unroll
            for (int mt = 0; mt < 4; ++mt)
                #pragma unroll
                for (int nt = 0; nt < 4; ++nt) {
                    const int bt = nt >> 1, h = (nt & 1) * 2;
                    mma_f16(acc[mt][nt], af[mt], bf[bt][h], bf[bt][h + 1]);
                }
        }
        __syncthreads();
    }

    // ---- epilogue ----
    const int gr0 = row0 + wm * 64 + (lane >> 2);
    const int gc0 = col0 + wn * 32 + (lane & 3) * 2;

    #pragma unroll
    for (int mt = 0; mt < 4; ++mt)
        #pragma unroll
        for (int nt = 0; nt < 4; ++nt) {
            const int gr = gr0 + mt * 16;
            const int gc = gc0 + nt * 8;
            const float* c = acc[mt][nt];
            if (MODE == 0) {
                if (z == 2) {            // V: fp16, transposed Vt[(b*1024+n)][t]
                    const int b = gr >> 11, t = gr & 2047;
                    const size_t o = ((size_t)(b * 1024 + gc)) * 2048 + t;
                    g_Vt[o]            = __float2half(c[0]);
                    g_Vt[o + 2048]     = __float2half(c[1]);
                    g_Vt[o + 8]        = __float2half(c[2]);
                    g_Vt[o + 2048 + 8] = __float2half(c[3]);
                } else {                 // Q or K: fp16 row-major
                    fp16* d = (z == 0) ? g_Q : g_K;
                    const size_t o = (size_t)gr * 1024 + gc;
                    *(__half2*)(d + o)            = __floats2half2_rn(c[0], c[1]);
                    *(__half2*)(d + o + 8 * 1024) = __floats2half2_rn(c[2], c[3]);
                }
            } else if (MODE == 1) {
                float* p = g_S + ((size_t)z << 22) + (size_t)gr * 2048 + gc;
                *(float2*)p              = make_float2(c[0] * 0.03125f, c[1] * 0.03125f);
                *(float2*)(p + 8 * 2048) = make_float2(c[2] * 0.03125f, c[3] * 0.03125f);
            } else {
                float* p = outp + ((size_t)z << 21) + (size_t)gr * 1024 + gc;
                *(float2*)p              = make_float2(c[0], c[1]);
                *(float2*)(p + 8 * 1024) = make_float2(c[2], c[3]);
            }
        }
}

// ---------------- softmax: one row (256 thr, 8 elems/thr) ---------------------
__device__ __forceinline__ void softmax_row(int rowid, float* red)
{
    size_t ro = (size_t)rowid * 2048;
    const float* p = g_S + ro;
    const int t = threadIdx.x;

    float v[8];
    float m = -1e30f;
    #pragma unroll
    for (int i = 0; i < 8; ++i) {
        v[i] = p[t + i * 256];
        m = fmaxf(m, v[i]);
    }
    #pragma unroll
    for (int o = 16; o; o >>= 1) m = fmaxf(m, __shfl_xor_sync(0xffffffffu, m, o));
    if ((t & 31) == 0) red[t >> 5] = m;
    __syncthreads();
    m = red[0];
    #pragma unroll
    for (int i = 1; i < 8; ++i) m = fmaxf(m, red[i]);
    __syncthreads();

    float s = 0.f;
    #pragma unroll
    for (int i = 0; i < 8; ++i) {
        v[i] = __expf(v[i] - m);
        s += v[i];
    }
    #pragma unroll
    for (int o = 16; o; o >>= 1) s += __shfl_xor_sync(0xffffffffu, s, o);
    if ((t & 31) == 0) red[t >> 5] = s;
    __syncthreads();
    s = red[0];
    #pragma unroll
    for (int i = 1; i < 8; ++i) s += red[i];

    const float inv = 1.0f / s;
    #pragma unroll
    for (int i = 0; i < 8; ++i) {
        size_t o = ro + t + i * 256;
        g_P[o] = __float2half(v[i] * inv);
    }
    __syncthreads();   // red[] reused by next row
}

// ---------------- launch 1: QKVproj + QK + softmax ----------------------------
__global__ void __launch_bounds__(256)
mega_kernel()
{
    const int b = blockIdx.x;
    if (b < 1024) {                     // ---- Q/K projections ----
        const int z = b >> 9, r = b & 511;
        const int by = r >> 3;
        gemm_body<0>(g_x, 1024, g_W + (size_t)z * 1024 * 1024, 1024,
                     1024, nullptr, r & 7, by, z);
        arrive(z * 64 + by);
    } else if (b < 1536) {              // ---- V projection ----
        const int r = b - 1024;
        gemm_body<0>(g_x, 1024, g_W + (size_t)2 * 1024 * 1024, 1024,
                     1024, nullptr, r & 7, r >> 3, 2);
    } else if (b < 2560) {              // ---- QK tiles ----
        const int j = b - 1536;
        const int z = j >> 8, by = (j >> 4) & 15, bx = j & 15;
        spin_until(&g_cnt[z * 16 + by], 8);          // Q row-block
        spin_until(&g_cnt[64 + z * 16 + bx], 8);     // K row-block
        __syncthreads();
        const size_t bo = (size_t)z << 21;
        gemm_body<1>(g_Q + bo, 1024, g_K + bo, 1024, 1024, nullptr, bx, by, z);
        arrive(128 + z * 16 + by);                   // S row-block (16 arrivals)
    } else {                            // ---- softmax: 8 rows per CTA ----
        const int j = b - 2560;                      // 0..1023
        const int rb = j >> 4;                       // S row-block 0..63
        spin_until(&g_cnt[128 + rb], 16);
        __syncthreads();
        __shared__ float red[8];
        const int row0 = rb * 128 + (j & 15) * 8;
        #pragma unroll 1
        for (int r = 0; r < 8; ++r) softmax_row(row0 + r, red);
    }
}

// ---------------- launch 2: PV (standard grid) --------------------------------
__global__ void __launch_bounds__(256)
pv_kernel(float* __restrict__ out)
{
    const size_t ao = (size_t)blockIdx.z << 22;   // b*2048*2048
    const size_t bo = (size_t)blockIdx.z << 21;   // b*1024*2048
    gemm_body<2>(g_P + ao, 2048, g_Vt + bo, 2048, 2048, out,
                 blockIdx.x, blockIdx.y, blockIdx.z);
}

// One launch converting x then Wq/Wk/Wv; block 0 also zeroes the dep counters.
#define N4_X (8192 * 1024 / 4)
#define N4_W (1024 * 1024 / 4)
__global__ void __launch_bounds__(256)
convert_all_kernel(const float* __restrict__ x, const float* __restrict__ Wq,
                   const float* __restrict__ Wk, const float* __restrict__ Wv)
{
    if (blockIdx.x == 0) {
        for (int i = threadIdx.x; i < 192; i += 256) g_cnt[i] = 0;
    }

    const int i = blockIdx.x * blockDim.x + threadIdx.x;
    const float* src;
    fp16* dst;
    int k;
    if (i < N4_X) {
        src = x; dst = g_x; k = i;
    } else {
        int j = i - N4_X;
        int w = j / N4_W;
        k = j - w * N4_W;
        src = (w == 0) ? Wq : (w == 1) ? Wk : Wv;
        dst = g_W + (size_t)w * 1024 * 1024;
    }
    float4 v = *(const float4*)(src + (size_t)k * 4);
    __half2* d = (__half2*)(dst + (size_t)k * 4);
    d[0] = __floats2half2_rn(v.x, v.y);
    d[1] = __floats2half2_rn(v.z, v.w);
}

// ---------------- launch ------------------------------------------------------
extern "C" void kernel_launch(void* const* d_in, const int* in_sizes, int n_in,
                              void* d_out, int out_size)
{
    const float* x  = (const float*)d_in[0];
    const float* Wq = (const float*)d_in[1];
    const float* Wk = (const float*)d_in[2];
    const float* Wv = (const float*)d_in[3];
    float* out = (float*)d_out;

    cudaFuncSetAttribute(mega_kernel, cudaFuncAttributeMaxDynamicSharedMemorySize, SM_TOTAL);
    cudaFuncSetAttribute(pv_kernel,   cudaFuncAttributeMaxDynamicSharedMemorySize, SM_TOTAL);

    {
        int n4 = N4_X + 3 * N4_W;
        convert_all_kernel<<<(n4 + 255) / 256, 256>>>(x, Wq, Wk, Wv);
    }

    // launch 1: QKproj(1024) + Vproj(512) + QK(1024) + softmax(1024)
    mega_kernel<<<3584, 256, SM_TOTAL>>>();

    // launch 2: PV (standard grid)
    dim3 g3(8, 16, 4);
    pv_kernel<<<g3, 256, SM_TOTAL>>>(out);
}

// round 16
// speedup vs baseline: 1.0547x; 1.0402x over previous
#include <cuda_runtime.h>
#include <cuda_fp16.h>
#include <cstdint>

// ============================================================================
// R16: R12 structure (the proven fusion optimum: mega = QKVproj + QK with
// producer-adjacent spinners; separate softmax; separate PV) with:
//  - S stored in fp16 (halves QK-epilogue store + softmax read traffic;
//    adds one ~2e-4 logit quantization -> predicted rel_err ~6.2e-4)
//  - softmax fully coalesced (uint4 = 8 contiguous halves per thread)
//  - convert kernel processes 2 float4 chunks/thread (MLP 2)
// ============================================================================

using fp16 = __half;

// ---------------- scratch ----------------------------------------------------
__device__ __align__(256) fp16 g_x[8192 * 1024];
__device__ __align__(256) fp16 g_W[3 * 1024 * 1024];
__device__ __align__(256) fp16 g_Q[8192 * 1024];
__device__ __align__(256) fp16 g_K[8192 * 1024];
__device__ __align__(256) fp16 g_Vt[4 * 1024 * 2048];        // transposed
__device__ __align__(256) fp16 g_S[4 * 2048 * 2048];         // fp16 scores (R16)
__device__ __align__(256) fp16 g_P[4 * 2048 * 2048];
__device__ int g_cnt[128];      // [0,64): Q row-blocks, [64,128): K row-blocks

// ---------------- PTX helpers -------------------------------------------------
__device__ __forceinline__ uint32_t smem_u32(const void* p) {
    uint32_t a;
    asm("{ .reg .u64 t; cvta.to.shared.u64 t, %1; cvt.u32.u64 %0, t; }" : "=r"(a) : "l"(p));
    return a;
}
__device__ __forceinline__ void cp16(uint32_t dst, const void* src) {
    asm volatile("cp.async.cg.shared.global [%0], [%1], 16;" :: "r"(dst), "l"(src));
}
#define CP_COMMIT() asm volatile("cp.async.commit_group;" ::: "memory")

__device__ __forceinline__ void ldm4(uint32_t* r, uint32_t a) {
    asm volatile("ldmatrix.sync.aligned.m8n8.x4.shared.b16 {%0,%1,%2,%3}, [%4];"
                 : "=r"(r[0]), "=r"(r[1]), "=r"(r[2]), "=r"(r[3]) : "r"(a));
}
__device__ __forceinline__ void mma_f16(float* c, const uint32_t* a, uint32_t b0, uint32_t b1) {
    asm volatile(
        "mma.sync.aligned.m16n8k16.row.col.f32.f16.f16.f32 "
        "{%0,%1,%2,%3}, {%4,%5,%6,%7}, {%8,%9}, {%0,%1,%2,%3};"
        : "+f"(c[0]), "+f"(c[1]), "+f"(c[2]), "+f"(c[3])
        : "r"(a[0]), "r"(a[1]), "r"(a[2]), "r"(a[3]), "r"(b0), "r"(b1));
}
__device__ __forceinline__ int ld_acq(const int* p) {
    int v;
    asm volatile("ld.acquire.gpu.global.b32 %0, [%1];" : "=r"(v) : "l"(p) : "memory");
    return v;
}
__device__ __forceinline__ void spin_until(const int* c, int target) {
    if (threadIdx.x == 0) {
        while (ld_acq(c) < target) __nanosleep(64);
    }
}
__device__ __forceinline__ void arrive(int idx) {
    __threadfence();
    __syncthreads();
    if (threadIdx.x == 0) atomicAdd(&g_cnt[idx], 1);
}

// ---------------- SMEM layout -------------------------------------------------
// Per stage: A, B — each 128 rows x 64 fp16 (128B data), row stride 144B.
// ldmatrix phase (8 rows): banks 36r ≡ 4r mod 32, distinct. Conflict-free.
#define ROWB     144
#define ARR_B    (128 * ROWB)          // 18432
#define STG_B    (2 * ARR_B)           // 36864
#define SM_TOTAL (2 * STG_B)           // 73728

// ---------------- GEMM body: 128x128 tile, 256 thr, warps 2(m) x 4(n) --------
// MODE 0: QKV (z: 0->Q, 1->K, 2->V transposed) -> fp16
// MODE 1: QK  (z=batch), g_S = fp16(acc/32)
// MODE 2: PV  (z=batch), out = acc fp32
template <int MODE>
__device__ __forceinline__ void gemm_body(
    const fp16* __restrict__ A, int lda,
    const fp16* __restrict__ B, int ldb,
    int K, float* __restrict__ outp,
    int bx, int by, int z)
{
    extern __shared__ char sm[];
    const uint32_t smb = smem_u32(sm);
    const int tid = threadIdx.x, lane = tid & 31, wid = tid >> 5;
    const int wm = wid & 1, wn = wid >> 1;          // warp tile: 64x32
    const int row0 = by * 128, col0 = bx * 128;

    float acc[4][4][4];
    #pragma unroll
    for (int i = 0; i < 4; ++i)
        #pragma unroll
        for (int j = 0; j < 4; ++j)
            #pragma unroll
            for (int k = 0; k < 4; ++k) acc[i][j][k] = 0.f;

    const fp16* pa = A + (size_t)row0 * lda;
    const fp16* pb = B + (size_t)col0 * ldb;

    auto load_stage = [&](int sbuf, int k0) {
        const uint32_t b = smb + sbuf * STG_B;
        #pragma unroll
        for (int v = 0; v < 4; ++v) {
            const int idx = tid + v * 256;       // 0..1023
            const int row = idx >> 3;            // 0..127
            const int kc  = idx & 7;             // 16B unit
            const uint32_t so = row * ROWB + kc * 16;
            cp16(b + so,         pa + (size_t)row * lda + k0 + kc * 8);
            cp16(b + ARR_B + so, pb + (size_t)row * ldb + k0 + kc * 8);
        }
        CP_COMMIT();
    };

    const int ns = K >> 6;   // 64 K per stage
    load_stage(0, 0);

    const uint32_t a_off = (wm * 64 + (lane & 15)) * ROWB + (lane >> 4) * 16;
    const uint32_t b_off = ARR_B
                         + (wn * 32 + (lane & 7) + ((lane >> 4) << 3)) * ROWB
                         + ((lane >> 3) & 1) * 16;

    for (int s = 0; s < ns; ++s) {
        if (s + 1 < ns) {
            load_stage((s + 1) & 1, (s + 1) * 64);
            asm volatile("cp.async.wait_group 1;" ::: "memory");
        } else {
            asm volatile("cp.async.wait_group 0;" ::: "memory");
        }
        __syncthreads();

        const uint32_t sb = smb + (s & 1) * STG_B;
        #pragma unroll
        for (int ks = 0; ks < 4; ++ks) {         // 4 k16 slices per stage
            const uint32_t ab = sb + a_off + ks * 32;
            const uint32_t bb = sb + b_off + ks * 32;
            uint32_t af[4][4], bf[2][4];
            #pragma unroll
            for (int mt = 0; mt < 4; ++mt)
                ldm4(af[mt], ab + mt * 16 * ROWB);
            #pragma unroll
            for (int bt = 0; bt < 2; ++bt)
                ldm4(bf[bt], bb + bt * 16 * ROWB);
            #pragma unroll
            for (int mt = 0; mt < 4; ++mt)
                #pragma unroll
                for (int nt = 0; nt < 4; ++nt) {
                    const int bt = nt >> 1, h = (nt & 1) * 2;
                    mma_f16(acc[mt][nt], af[mt], bf[bt][h], bf[bt][h + 1]);
                }
        }
        __syncthreads();
    }

    // ---- epilogue ----
    const int gr0 = row0 + wm * 64 + (lane >> 2);
    const int gc0 = col0 + wn * 32 + (lane & 3) * 2;

    #pragma unroll
    for (int mt = 0; mt < 4; ++mt)
        #pragma unroll
        for (int nt = 0; nt < 4; ++nt) {
            const int gr = gr0 + mt * 16;
            const int gc = gc0 + nt * 8;
            const float* c = acc[mt][nt];
            if (MODE == 0) {
                if (z == 2) {            // V: fp16, transposed Vt[(b*1024+n)][t]
                    const int b = gr >> 11, t = gr & 2047;
                    const size_t o = ((size_t)(b * 1024 + gc)) * 2048 + t;
                    g_Vt[o]            = __float2half(c[0]);
                    g_Vt[o + 2048]     = __float2half(c[1]);
                    g_Vt[o + 8]        = __float2half(c[2]);
                    g_Vt[o + 2048 + 8] = __float2half(c[3]);
                } else {                 // Q or K: fp16 row-major
                    fp16* d = (z == 0) ? g_Q : g_K;
                    const size_t o = (size_t)gr * 1024 + gc;
                    *(__half2*)(d + o)            = __floats2half2_rn(c[0], c[1]);
                    *(__half2*)(d + o + 8 * 1024) = __floats2half2_rn(c[2], c[3]);
                }
            } else if (MODE == 1) {      // S: fp16 (R16)
                fp16* p = g_S + ((size_t)z << 22) + (size_t)gr * 2048 + gc;
                *(__half2*)p             = __floats2half2_rn(c[0] * 0.03125f, c[1] * 0.03125f);
                *(__half2*)(p + 8*2048)  = __floats2half2_rn(c[2] * 0.03125f, c[3] * 0.03125f);
            } else {
                float* p = outp + ((size_t)z << 21) + (size_t)gr * 1024 + gc;
                *(float2*)p              = make_float2(c[0], c[1]);
                *(float2*)(p + 8 * 1024) = make_float2(c[2], c[3]);
            }
        }
}

// ---------------- launch 1: QKVproj + QK (R12 mega) ---------------------------
__global__ void __launch_bounds__(256)
mega_kernel()
{
    const int b = blockIdx.x;
    if (b < 1024) {                     // Q/K projections: z = b/512
        const int z = b >> 9, r = b & 511;
        const int by = r >> 3;
        gemm_body<0>(g_x, 1024, g_W + (size_t)z * 1024 * 1024, 1024,
                     1024, nullptr, r & 7, by, z);
        arrive(z * 64 + by);
    } else if (b < 1536) {              // V projection
        const int r = b - 1024;
        gemm_body<0>(g_x, 1024, g_W + (size_t)2 * 1024 * 1024, 1024,
                     1024, nullptr, r & 7, r >> 3, 2);
    } else {                            // QK tiles, spin on Q/K row blocks
        const int j = b - 1536;
        const int z = j >> 8, by = (j >> 4) & 15, bx = j & 15;
        spin_until(&g_cnt[z * 16 + by], 8);          // Q row-block
        spin_until(&g_cnt[64 + z * 16 + bx], 8);     // K row-block
        __syncthreads();
        const size_t bo = (size_t)z << 21;
        gemm_body<1>(g_Q + bo, 1024, g_K + bo, 1024, 1024, nullptr, bx, by, z);
    }
}

// ---------------- softmax: fp16 S in, fp16 P out, fully coalesced -------------
__global__ void __launch_bounds__(256)
softmax_kernel()
{
    const size_t ro = (size_t)blockIdx.x * 2048;
    const int t = threadIdx.x;
    __shared__ float red[8];

    // 8 contiguous halves per thread (16B)
    uint4 raw = *(const uint4*)(g_S + ro + t * 8);
    float v[8];
    {
        const __half2* h2 = (const __half2*)&raw;
        #pragma unroll
        for (int i = 0; i < 4; ++i) {
            float2 f = __half22float2(h2[i]);
            v[i * 2] = f.x;
            v[i * 2 + 1] = f.y;
        }
    }

    float m = -1e30f;
    #pragma unroll
    for (int i = 0; i < 8; ++i) m = fmaxf(m, v[i]);
    #pragma unroll
    for (int o = 16; o; o >>= 1) m = fmaxf(m, __shfl_xor_sync(0xffffffffu, m, o));
    if ((t & 31) == 0) red[t >> 5] = m;
    __syncthreads();
    m = red[0];
    #pragma unroll
    for (int i = 1; i < 8; ++i) m = fmaxf(m, red[i]);
    __syncthreads();

    float s = 0.f;
    #pragma unroll
    for (int i = 0; i < 8; ++i) {
        v[i] = __expf(v[i] - m);
        s += v[i];
    }
    #pragma unroll
    for (int o = 16; o; o >>= 1) s += __shfl_xor_sync(0xffffffffu, s, o);
    if ((t & 31) == 0) red[t >> 5] = s;
    __syncthreads();
    s = red[0];
    #pragma unroll
    for (int i = 1; i < 8; ++i) s += red[i];

    const float inv = 1.0f / s;
    uint4 outw;
    __half2* o2 = (__half2*)&outw;
    #pragma unroll
    for (int i = 0; i < 4; ++i)
        o2[i] = __floats2half2_rn(v[i * 2] * inv, v[i * 2 + 1] * inv);
    *(uint4*)(g_P + ro + t * 8) = outw;
}

// ---------------- launch 2: PV (standard grid) --------------------------------
__global__ void __launch_bounds__(256)
pv_kernel(float* __restrict__ out)
{
    const size_t ao = (size_t)blockIdx.z << 22;   // b*2048*2048
    const size_t bo = (size_t)blockIdx.z << 21;   // b*1024*2048
    gemm_body<2>(g_P + ao, 2048, g_Vt + bo, 2048, 2048, out,
                 blockIdx.x, blockIdx.y, blockIdx.z);
}

// Convert: 2 float4 chunks per thread (MLP 2); block 0 zeroes dep counters.
#define N4_X (8192 * 1024 / 4)
#define N4_W (1024 * 1024 / 4)
#define N4_TOT (N4_X + 3 * N4_W)       // 2883584
__device__ __forceinline__ void convert_chunk(
    int c, const float* __restrict__ x, const float* __restrict__ Wq,
    const float* __restrict__ Wk, const float* __restrict__ Wv)
{
    const float* src;
    fp16* dst;
    int k;
    if (c < N4_X) {
        src = x; dst = g_x; k = c;
    } else {
        int j = c - N4_X;
        int w = j / N4_W;
        k = j - w * N4_W;
        src = (w == 0) ? Wq : (w == 1) ? Wk : Wv;
        dst = g_W + (size_t)w * 1024 * 1024;
    }
    float4 v = *(const float4*)(src + (size_t)k * 4);
    __half2* d = (__half2*)(dst + (size_t)k * 4);
    d[0] = __floats2half2_rn(v.x, v.y);
    d[1] = __floats2half2_rn(v.z, v.w);
}

__global__ void __launch_bounds__(256)
convert_all_kernel(const float* __restrict__ x, const float* __restrict__ Wq,
                   const float* __restrict__ Wk, const float* __restrict__ Wv)
{
    if (blockIdx.x == 0) {
        for (int i = threadIdx.x; i < 128; i += 256) g_cnt[i] = 0;
    }
    const int i = blockIdx.x * blockDim.x + threadIdx.x;
    const int c0 = i * 2;
    if (c0 < N4_TOT)     convert_chunk(c0,     x, Wq, Wk, Wv);
    if (c0 + 1 < N4_TOT) convert_chunk(c0 + 1, x, Wq, Wk, Wv);
}

// ---------------- launch ------------------------------------------------------
extern "C" void kernel_launch(void* const* d_in, const int* in_sizes, int n_in,
                              void* d_out, int out_size)
{
    const float* x  = (const float*)d_in[0];
    const float* Wq = (const float*)d_in[1];
    const float* Wk = (const float*)d_in[2];
    const float* Wv = (const float*)d_in[3];
    float* out = (float*)d_out;

    cudaFuncSetAttribute(mega_kernel, cudaFuncAttributeMaxDynamicSharedMemorySize, SM_TOTAL);
    cudaFuncSetAttribute(pv_kernel,   cudaFuncAttributeMaxDynamicSharedMemorySize, SM_TOTAL);

    {
        int nthr = (N4_TOT + 1) / 2;
        convert_all_kernel<<<(nthr + 255) / 256, 256>>>(x, Wq, Wk, Wv);
    }

    // launch 1: QKproj(1024) + Vproj(512) + QK(1024)
    mega_kernel<<<2560, 256, SM_TOTAL>>>();

    softmax_kernel<<<4 * 2048, 256>>>();

    // launch 2: PV
    dim3 g3(8, 16, 4);
    pv_kernel<<<g3, 256, SM_TOTAL>>>(out);
}